// round 17
// baseline (speedup 1.0000x reference)
#include <cuda_runtime.h>

// hidden [4096] f32, encoder_outputs [8192,1,4096] f32
// energies = enc @ hidden -> softmax -> output = enc^T @ attn
// d_out: [0:4096) = output, [4096:12288) = attn
//
// SINGLE persistent kernel (256 co-resident blocks, 2/SM), software-pipelined
// streaming: next group's loads issued before current group's reduce.
// Grid barrier, then atomic-free combine (block owns 16 out cols + 32 attn).

#define SEQ_LEN 8192
#define HIDDEN  4096
#define H4      (HIDDEN / 4)
#define NBLK    256
#define ROWS    (SEQ_LEN / NBLK)   // 32 rows per block
#define GRP     2                  // rows per pipeline stage
#define NGRP    (ROWS / GRP)       // 16

__device__ float g_energies[SEQ_LEN];
__device__ float g_partial[(size_t)NBLK * HIDDEN];
__device__ float g_m[NBLK];
__device__ float g_l[NBLK];
__device__ int   g_count;          // arrivals; reset by last block
__device__ int   g_phase;          // monotonically increasing release flag

__global__ __launch_bounds__(256, 2) void attn_fused(
    const float* __restrict__ enc, const float* __restrict__ hidden,
    float* __restrict__ out, float* __restrict__ attn)
{
    const int tid  = threadIdx.x;
    const int wid  = tid >> 5;
    const int lane = tid & 31;
    const int bid  = blockIdx.x;
    const int r0   = bid * ROWS;

    __shared__ float  sred[2][GRP][8];
    __shared__ float4 sacc[256][4];      // 16 KB combine tree
    __shared__ float  red2[8];
    __shared__ float  sM, sZ;
    __shared__ int    s_phase;

    if (tid == 0) s_phase = *(volatile int*)&g_phase;
    __syncthreads();
    const int myphase = s_phase;

    // ---- phase A: pipelined online-softmax accumulation over 32 rows ------
    const float4* h4 = reinterpret_cast<const float4*>(hidden);
    float4 hv0 = h4[tid];
    float4 hv1 = h4[tid + 256];
    float4 hv2 = h4[tid + 512];
    float4 hv3 = h4[tid + 768];

    float4 acc[4];
    #pragma unroll
    for (int k = 0; k < 4; ++k) acc[k] = make_float4(0.f, 0.f, 0.f, 0.f);
    float m = -3.4e38f;
    float l = 0.f;

    float4 d[2][GRP][4];               // double buffer

    // prologue: load group 0 into buffer 0
    #pragma unroll
    for (int s = 0; s < GRP; ++s) {
        const float4* b = reinterpret_cast<const float4*>(enc + (size_t)(r0 + s) * HIDDEN);
        d[0][s][0] = __ldcs(b + tid);
        d[0][s][1] = __ldcs(b + tid + 256);
        d[0][s][2] = __ldcs(b + tid + 512);
        d[0][s][3] = __ldcs(b + tid + 768);
    }

    #pragma unroll 1
    for (int g = 0; g < NGRP; ++g) {
        const int cur = g & 1;
        const int nxt = cur ^ 1;
        const int rg  = r0 + g * GRP;

        // issue NEXT group's loads before touching current data
        if (g + 1 < NGRP) {
            const int rn = r0 + (g + 1) * GRP;
            #pragma unroll
            for (int s = 0; s < GRP; ++s) {
                const float4* b = reinterpret_cast<const float4*>(enc + (size_t)(rn + s) * HIDDEN);
                d[nxt][s][0] = __ldcs(b + tid);
                d[nxt][s][1] = __ldcs(b + tid + 256);
                d[nxt][s][2] = __ldcs(b + tid + 512);
                d[nxt][s][3] = __ldcs(b + tid + 768);
            }
        }

        // dot products of current group
        float dot[GRP];
        #pragma unroll
        for (int s = 0; s < GRP; ++s) {
            dot[s] = d[cur][s][0].x*hv0.x + d[cur][s][0].y*hv0.y + d[cur][s][0].z*hv0.z + d[cur][s][0].w*hv0.w
                   + d[cur][s][1].x*hv1.x + d[cur][s][1].y*hv1.y + d[cur][s][1].z*hv1.z + d[cur][s][1].w*hv1.w
                   + d[cur][s][2].x*hv2.x + d[cur][s][2].y*hv2.y + d[cur][s][2].z*hv2.z + d[cur][s][2].w*hv2.w
                   + d[cur][s][3].x*hv3.x + d[cur][s][3].y*hv3.y + d[cur][s][3].z*hv3.z + d[cur][s][3].w*hv3.w;
        }
        #pragma unroll
        for (int off = 16; off > 0; off >>= 1) {
            #pragma unroll
            for (int s = 0; s < GRP; ++s)
                dot[s] += __shfl_down_sync(0xFFFFFFFFu, dot[s], off);
        }
        if (lane == 0) {
            #pragma unroll
            for (int s = 0; s < GRP; ++s) sred[cur][s][wid] = dot[s];
        }
        __syncthreads();

        float e[GRP];
        #pragma unroll
        for (int s = 0; s < GRP; ++s)
            e[s] = sred[cur][s][0] + sred[cur][s][1] + sred[cur][s][2] + sred[cur][s][3]
                 + sred[cur][s][4] + sred[cur][s][5] + sred[cur][s][6] + sred[cur][s][7];
        if (tid < GRP) g_energies[rg + tid] = e[tid];

        // online rescale with current group
        float mg = fmaxf(e[0], e[1]);
        float mn = fmaxf(m, mg);
        float sc = __expf(m - mn);
        float p[GRP];
        float ps = 0.f;
        #pragma unroll
        for (int s = 0; s < GRP; ++s) { p[s] = __expf(e[s] - mn); ps += p[s]; }

        #pragma unroll
        for (int k = 0; k < 4; ++k) {
            acc[k].x *= sc; acc[k].y *= sc; acc[k].z *= sc; acc[k].w *= sc;
        }
        #pragma unroll
        for (int s = 0; s < GRP; ++s) {
            #pragma unroll
            for (int k = 0; k < 4; ++k) {
                acc[k].x += p[s] * d[cur][s][k].x;
                acc[k].y += p[s] * d[cur][s][k].y;
                acc[k].z += p[s] * d[cur][s][k].z;
                acc[k].w += p[s] * d[cur][s][k].w;
            }
        }
        l = l * sc + ps;
        m = mn;
    }

    float4* gp = reinterpret_cast<float4*>(g_partial + (size_t)bid * HIDDEN);
    gp[tid]       = acc[0];
    gp[tid + 256] = acc[1];
    gp[tid + 512] = acc[2];
    gp[tid + 768] = acc[3];
    if (tid == 0) { g_m[bid] = m; g_l[bid] = l; }

    // ---- grid barrier (all 256 blocks co-resident) -------------------------
    __threadfence();
    __syncthreads();
    if (tid == 0) {
        int t = atomicAdd(&g_count, 1);
        if (t == NBLK - 1) {
            g_count = 0;
            __threadfence();
            atomicExch(&g_phase, myphase + 1);
        } else {
            while (*(volatile int*)&g_phase == myphase) __nanosleep(64);
        }
    }
    __syncthreads();
    __threadfence();

    // ---- phase B: global stats (parallel, L2-hot) --------------------------
    float mt = g_m[tid];
    float lt = g_l[tid];

    float mv = mt;
    #pragma unroll
    for (int off = 16; off > 0; off >>= 1)
        mv = fmaxf(mv, __shfl_xor_sync(0xFFFFFFFFu, mv, off));
    if (lane == 0) red2[wid] = mv;
    __syncthreads();
    if (tid == 0) {
        float v = red2[0];
        #pragma unroll
        for (int i = 1; i < 8; ++i) v = fmaxf(v, red2[i]);
        sM = v;
    }
    __syncthreads();
    const float M = sM;

    float wexp = __expf(mt - M);
    float zt = lt * wexp;
    #pragma unroll
    for (int off = 16; off > 0; off >>= 1)
        zt += __shfl_xor_sync(0xFFFFFFFFu, zt, off);
    if (lane == 0) red2[wid] = zt;
    __syncthreads();
    if (tid == 0) {
        float v = red2[0];
        #pragma unroll
        for (int i = 1; i < 8; ++i) v += red2[i];
        sZ = v;
    }
    __syncthreads();
    const float invZ = 1.0f / sZ;
    const float wt = wexp * invZ;        // weight of partial-row `tid`

    // ---- phase C: combine — block owns float4 cols [4*bid, 4*bid+4) --------
    {
        const float4* pr = reinterpret_cast<const float4*>(g_partial + (size_t)tid * HIDDEN)
                         + bid * 4;
        #pragma unroll
        for (int k = 0; k < 4; ++k) {
            float4 v = pr[k];
            v.x *= wt; v.y *= wt; v.z *= wt; v.w *= wt;
            sacc[tid][k] = v;
        }
        __syncthreads();
        #pragma unroll
        for (int s = 128; s > 0; s >>= 1) {
            if (tid < s) {
                #pragma unroll
                for (int k = 0; k < 4; ++k) {
                    float4 a = sacc[tid][k];
                    float4 b = sacc[tid + s][k];
                    a.x += b.x; a.y += b.y; a.z += b.z; a.w += b.w;
                    sacc[tid][k] = a;
                }
            }
            __syncthreads();
        }
        if (tid < 16)
            out[bid * 16 + tid] = reinterpret_cast<const float*>(&sacc[0][0])[tid];
    }

    // ---- attn: block owns rows [32*bid, 32*bid+32) -------------------------
    if (tid < 32) {
        const int i = bid * 32 + tid;
        attn[i] = __expf(g_energies[i] - M) * invZ;
    }
}

extern "C" void kernel_launch(void* const* d_in, const int* in_sizes, int n_in,
                              void* d_out, int out_size)
{
    const float* hidden = (const float*)d_in[0];
    const float* enc    = (const float*)d_in[1];
    float* out  = (float*)d_out;
    float* attn = (float*)d_out + HIDDEN;

    attn_fused<<<NBLK, 256>>>(enc, hidden, out, attn);
}